// round 1
// baseline (speedup 1.0000x reference)
#include <cuda_runtime.h>
#include <math.h>

#define BB 2
#define SS 2048
#define DDIM 1024
#define HH 16
#define DK 64
#define MROWS 4096   // B*S

// ---------------- device scratch (no allocations allowed) ----------------
__device__ float g_Q[BB*HH*SS*DK];
__device__ float g_K[BB*HH*SS*DK];
__device__ float g_V[BB*HH*SS*DK];
__device__ float g_ctx[MROWS*DDIM];
__device__ float g_bd[HH*4096];     // bias as function of (h, delta+2047)

// ---------------- bias precompute: bucket(delta) -> table ----------------
__global__ void bias_precompute_kernel(const float* __restrict__ table) {
    int idx = blockIdx.x * blockDim.x + threadIdx.x;
    if (idx >= 4096) return;
    int delta = idx - 2047;                 // k - q
    int bucket = (delta > 0) ? 16 : 0;
    int rp = delta < 0 ? -delta : delta;
    int add;
    if (rp < 8) {
        add = rp;
    } else {
        // match reference op order: log(rp/8)/log(16)*8, truncate, +8, min 15
        float v = logf((float)rp / 8.0f) / logf(16.0f) * 8.0f;
        int vi = 8 + (int)v;
        add = vi < 15 ? vi : 15;
    }
    bucket += add;
    #pragma unroll
    for (int h = 0; h < HH; h++)
        g_bd[h*4096 + idx] = table[bucket*HH + h];
}

// ---------------- position_bias writer: out[h][q][k] = bd[h][k-q+2047] ----------------
__global__ void bias_out_kernel(float* __restrict__ out) {
    long long i4 = (long long)blockIdx.x * blockDim.x + threadIdx.x; // float4 index
    const long long per_h = (long long)SS * SS / 4;                  // 1048576
    int h = (int)(i4 / per_h);
    long long rem = i4 - (long long)h * per_h;
    int q = (int)(rem / (SS/4));
    int k4 = (int)(rem % (SS/4)) * 4;
    const float* row = g_bd + h*4096 + (k4 - q + 2047);
    float4 v = make_float4(row[0], row[1], row[2], row[3]);
    reinterpret_cast<float4*>(out)[i4] = v;
}

// ---------------- 128x128x8 fp32 SGEMM, M=4096 N=1024 K=1024 ----------------
// mode 0/1/2: C scattered into g_Q/g_K/g_V as [B,H,S,DK]
// mode 3:     A = g_ctx, C = Cout plain row-major [4096,1024]
__global__ __launch_bounds__(256, 2) void gemm128_kernel(
    const float* __restrict__ Ain, const float* __restrict__ W,
    float* __restrict__ Cout, int mode)
{
    __shared__ float As[8][128];
    __shared__ float Bs[8][128];
    const float* A = (mode == 3) ? (const float*)g_ctx : Ain;
    int tid = threadIdx.x;
    int tx = tid & 15, ty = tid >> 4;
    int row0 = blockIdx.y * 128, col0 = blockIdx.x * 128;

    float acc[8][8];
    #pragma unroll
    for (int i = 0; i < 8; i++)
        #pragma unroll
        for (int j = 0; j < 8; j++) acc[i][j] = 0.f;

    int ar  = tid >> 1;
    int akc = (tid & 1) * 4;
    int br  = tid >> 5;
    int bc  = (tid & 31) * 4;

    for (int k0 = 0; k0 < 1024; k0 += 8) {
        float4 av = *(const float4*)(A + (size_t)(row0 + ar) * 1024 + k0 + akc);
        As[akc+0][ar] = av.x; As[akc+1][ar] = av.y;
        As[akc+2][ar] = av.z; As[akc+3][ar] = av.w;
        *(float4*)&Bs[br][bc] = *(const float4*)(W + (size_t)(k0 + br) * 1024 + col0 + bc);
        __syncthreads();
        #pragma unroll
        for (int kk = 0; kk < 8; kk++) {
            float4 a0 = *(float4*)&As[kk][ty*8];
            float4 a1 = *(float4*)&As[kk][ty*8+4];
            float4 b0 = *(float4*)&Bs[kk][tx*8];
            float4 b1 = *(float4*)&Bs[kk][tx*8+4];
            float a[8] = {a0.x,a0.y,a0.z,a0.w,a1.x,a1.y,a1.z,a1.w};
            float b[8] = {b0.x,b0.y,b0.z,b0.w,b1.x,b1.y,b1.z,b1.w};
            #pragma unroll
            for (int i = 0; i < 8; i++)
                #pragma unroll
                for (int j = 0; j < 8; j++)
                    acc[i][j] += a[i] * b[j];
        }
        __syncthreads();
    }

    if (mode <= 2) {
        float* dst = (mode == 0) ? g_Q : (mode == 1) ? g_K : g_V;
        #pragma unroll
        for (int i = 0; i < 8; i++) {
            int r = row0 + ty*8 + i;
            int b = r >> 11, s = r & 2047;
            #pragma unroll
            for (int j = 0; j < 8; j++) {
                int c = col0 + tx*8 + j;
                int h = c >> 6, d = c & 63;
                dst[((size_t)(b*HH + h)*SS + s)*DK + d] = acc[i][j];
            }
        }
    } else {
        #pragma unroll
        for (int i = 0; i < 8; i++) {
            int r = row0 + ty*8 + i;
            float4 o0 = make_float4(acc[i][0],acc[i][1],acc[i][2],acc[i][3]);
            float4 o1 = make_float4(acc[i][4],acc[i][5],acc[i][6],acc[i][7]);
            *(float4*)(Cout + (size_t)r*1024 + col0 + tx*8)     = o0;
            *(float4*)(Cout + (size_t)r*1024 + col0 + tx*8 + 4) = o1;
        }
    }
}

// ---------------- flash attention: per (b,h), 128 q-rows per CTA ----------------
// dynamic smem layout (floats):
//   Qs   [128*64]          = 8192
//   Ks   [64*65]  (padded) = 4160
//   Vs   [64*64]           = 4096
//   Ps   [128*64]          = 8192
//   sbias[2176]
#define FL_SMEM_FLOATS (8192 + 4160 + 4096 + 8192 + 2176)

__global__ __launch_bounds__(256, 2) void flash_kernel() {
    extern __shared__ float sm[];
    float* Qs    = sm;
    float* Ks    = sm + 8192;
    float* Vs    = sm + 8192 + 4160;
    float* Ps    = sm + 8192 + 4160 + 4096;
    float* sbias = sm + 8192 + 4160 + 4096 + 8192;

    int tid = threadIdx.x;
    int tx = tid & 15, ty = tid >> 4;
    int q0 = blockIdx.x * 128;
    int bh = blockIdx.y;
    int h = bh & 15;
    const float* Qg = g_Q + (size_t)bh * SS * DK;
    const float* Kg = g_K + (size_t)bh * SS * DK;
    const float* Vg = g_V + (size_t)bh * SS * DK;

    // load Q tile [128][64]
    #pragma unroll
    for (int j = 0; j < 8; j++) {
        int f = tid + j*256;
        int r = f >> 4, c = (f & 15) << 2;
        *(float4*)&Qs[r*64 + c] = *(const float4*)(Qg + (size_t)(q0 + r)*64 + c);
    }
    // stage bias window: local i corresponds to global gidx = (1920 - q0) + i
    for (int i = tid; i < 2176; i += 256) {
        int gidx = (1920 - q0) + i;
        float v = 0.f;
        if (gidx >= 0 && gidx < 4096) v = g_bd[h*4096 + gidx];
        sbias[i] = v;
    }

    float m[8], l[8], acc[8][4];
    #pragma unroll
    for (int i = 0; i < 8; i++) {
        m[i] = -1e30f; l[i] = 0.f;
        #pragma unroll
        for (int j = 0; j < 4; j++) acc[i][j] = 0.f;
    }

    for (int kt = 0; kt < SS/64; kt++) {
        __syncthreads();   // previous PV done before overwriting K/V/P
        int kb0 = kt * 64;
        #pragma unroll
        for (int j = 0; j < 4; j++) {
            int f = tid + j*256;
            int r = f >> 4, c = (f & 15) << 2;
            float4 kv = *(const float4*)(Kg + (size_t)(kb0 + r)*64 + c);
            Ks[r*65 + c + 0] = kv.x; Ks[r*65 + c + 1] = kv.y;
            Ks[r*65 + c + 2] = kv.z; Ks[r*65 + c + 3] = kv.w;
            *(float4*)&Vs[r*64 + c] = *(const float4*)(Vg + (size_t)(kb0 + r)*64 + c);
        }
        __syncthreads();

        // S = Q @ K^T  (8x4 per thread)
        float sc[8][4];
        #pragma unroll
        for (int i = 0; i < 8; i++)
            #pragma unroll
            for (int j = 0; j < 4; j++) sc[i][j] = 0.f;

        #pragma unroll 4
        for (int d0 = 0; d0 < 64; d0++) {
            float k0v = Ks[(tx*4+0)*65 + d0];
            float k1v = Ks[(tx*4+1)*65 + d0];
            float k2v = Ks[(tx*4+2)*65 + d0];
            float k3v = Ks[(tx*4+3)*65 + d0];
            #pragma unroll
            for (int i = 0; i < 8; i++) {
                float qa = Qs[(ty*8+i)*64 + d0];
                sc[i][0] += qa * k0v;
                sc[i][1] += qa * k1v;
                sc[i][2] += qa * k2v;
                sc[i][3] += qa * k3v;
            }
        }

        // bias + online softmax
        #pragma unroll
        for (int i = 0; i < 8; i++) {
            int qrel = ty*8 + i;
            int kcol = kb0 + tx*4;
            sc[i][0] += sbias[kcol + 0 - qrel + 127];
            sc[i][1] += sbias[kcol + 1 - qrel + 127];
            sc[i][2] += sbias[kcol + 2 - qrel + 127];
            sc[i][3] += sbias[kcol + 3 - qrel + 127];

            float t = fmaxf(fmaxf(sc[i][0], sc[i][1]), fmaxf(sc[i][2], sc[i][3]));
            #pragma unroll
            for (int mk = 8; mk; mk >>= 1)
                t = fmaxf(t, __shfl_xor_sync(0xffffffffu, t, mk));
            float mn = fmaxf(m[i], t);
            float sum = 0.f;
            #pragma unroll
            for (int j = 0; j < 4; j++) {
                float p = __expf(sc[i][j] - mn);
                sc[i][j] = p; sum += p;
            }
            #pragma unroll
            for (int mk = 8; mk; mk >>= 1)
                sum += __shfl_xor_sync(0xffffffffu, sum, mk);
            float scale = __expf(m[i] - mn);
            l[i] = l[i]*scale + sum;
            m[i] = mn;
            #pragma unroll
            for (int j = 0; j < 4; j++) acc[i][j] *= scale;
            *(float4*)&Ps[(ty*8+i)*64 + tx*4] =
                make_float4(sc[i][0], sc[i][1], sc[i][2], sc[i][3]);
        }
        __syncthreads();

        // acc += P @ V
        #pragma unroll 4
        for (int kk = 0; kk < 64; kk++) {
            float4 vb = *(float4*)&Vs[kk*64 + tx*4];
            #pragma unroll
            for (int i = 0; i < 8; i++) {
                float pa = Ps[(ty*8+i)*64 + kk];
                acc[i][0] += pa * vb.x;
                acc[i][1] += pa * vb.y;
                acc[i][2] += pa * vb.z;
                acc[i][3] += pa * vb.w;
            }
        }
    }

    int b = bh >> 4;
    #pragma unroll
    for (int i = 0; i < 8; i++) {
        float inv = 1.0f / l[i];
        int s = q0 + ty*8 + i;
        float4 o = make_float4(acc[i][0]*inv, acc[i][1]*inv, acc[i][2]*inv, acc[i][3]*inv);
        *(float4*)&g_ctx[(size_t)(b*SS + s)*1024 + h*64 + tx*4] = o;
    }
}

// ---------------- launch ----------------
extern "C" void kernel_launch(void* const* d_in, const int* in_sizes, int n_in,
                              void* d_out, int out_size)
{
    const float* hidden = (const float*)d_in[0];
    const float* Wq     = (const float*)d_in[1];
    const float* Wk     = (const float*)d_in[2];
    const float* Wv     = (const float*)d_in[3];
    const float* Wo     = (const float*)d_in[4];
    const float* tbl    = (const float*)d_in[5];
    float* out = (float*)d_out;

    (void)in_sizes; (void)n_in;

    // 1. bias(delta) table
    bias_precompute_kernel<<<16, 256>>>(tbl);

    // 2. Q/K/V projections (scattered into [B,H,S,DK])
    dim3 ggrid(8, 32);
    gemm128_kernel<<<ggrid, 256>>>(hidden, Wq, nullptr, 0);
    gemm128_kernel<<<ggrid, 256>>>(hidden, Wk, nullptr, 1);
    gemm128_kernel<<<ggrid, 256>>>(hidden, Wv, nullptr, 2);

    // 3. flash attention -> g_ctx
    size_t flsmem = (size_t)FL_SMEM_FLOATS * sizeof(float);
    cudaFuncSetAttribute(flash_kernel,
                         cudaFuncAttributeMaxDynamicSharedMemorySize, (int)flsmem);
    dim3 fgrid(SS/128, BB*HH);
    flash_kernel<<<fgrid, 256, flsmem>>>();

    // 4. output projection -> d_out[0 .. 4194304)
    gemm128_kernel<<<ggrid, 256>>>(nullptr, Wo, out, 3);

    // 5. position_bias -> d_out[4194304 ..) if requested
    long long attn_elems = (long long)MROWS * DDIM;               // 4,194,304
    long long bias_elems = (long long)HH * SS * SS;               // 67,108,864
    if ((long long)out_size >= attn_elems + bias_elems) {
        int nblocks = (int)(bias_elems / 4 / 256);                // 65536
        bias_out_kernel<<<nblocks, 256>>>(out + attn_elems);
    }
}

// round 5
// speedup vs baseline: 2.0673x; 2.0673x over previous
#include <cuda_runtime.h>
#include <cuda_bf16.h>
#include <math.h>
#include <stdint.h>

#define BB 2
#define SS 2048
#define DDIM 1024
#define HH 16
#define DK 64
#define MROWS 4096   // B*S

typedef __nv_bfloat16 bf16;
typedef __nv_bfloat162 bf162;

// ---------------- device scratch ----------------
__device__ __align__(16) bf16 g_hhi[MROWS*DDIM];
__device__ __align__(16) bf16 g_hlo[MROWS*DDIM];
__device__ __align__(16) bf16 g_Wthi[4*DDIM*DDIM];   // [slot][n][k]
__device__ __align__(16) bf16 g_Wtlo[4*DDIM*DDIM];
__device__ __align__(16) bf16 g_Qhi[MROWS*DDIM];
__device__ __align__(16) bf16 g_Qlo[MROWS*DDIM];
__device__ __align__(16) bf16 g_Khi[MROWS*DDIM];
__device__ __align__(16) bf16 g_Klo[MROWS*DDIM];
__device__ __align__(16) bf16 g_Vhi[MROWS*DDIM];
__device__ __align__(16) bf16 g_Vlo[MROWS*DDIM];
__device__ __align__(16) bf16 g_chi[MROWS*DDIM];
__device__ __align__(16) bf16 g_clo[MROWS*DDIM];
__device__ __align__(16) float g_bd[HH*4096];

// ---------------- low-level helpers ----------------
__device__ __forceinline__ uint32_t smem_u32(const void* p) {
    uint32_t a;
    asm("{ .reg .u64 t; cvta.to.shared.u64 t, %1; cvt.u32.u64 %0, t; }" : "=r"(a) : "l"(p));
    return a;
}
__device__ __forceinline__ uint32_t lds32(uint32_t a) {
    uint32_t v; asm volatile("ld.shared.b32 %0, [%1];" : "=r"(v) : "r"(a)); return v;
}
__device__ __forceinline__ void sts16(uint32_t a, unsigned short v) {
    asm volatile("st.shared.u16 [%0], %1;" :: "r"(a), "h"(v));
}
__device__ __forceinline__ void cp16(uint32_t dst, const void* src) {
    asm volatile("cp.async.ca.shared.global [%0], [%1], 16;" :: "r"(dst), "l"(src));
}
#define CP_COMMIT() asm volatile("cp.async.commit_group;" ::: "memory")
#define CP_WAIT(N)  asm volatile("cp.async.wait_group %0;" :: "n"(N) : "memory")

__device__ __forceinline__ void mma16816(float* c, const uint32_t* a, uint32_t b0, uint32_t b1) {
    asm volatile("mma.sync.aligned.m16n8k16.row.col.f32.bf16.bf16.f32 "
        "{%0,%1,%2,%3}, {%4,%5,%6,%7}, {%8,%9}, {%0,%1,%2,%3};"
        : "+f"(c[0]), "+f"(c[1]), "+f"(c[2]), "+f"(c[3])
        : "r"(a[0]), "r"(a[1]), "r"(a[2]), "r"(a[3]), "r"(b0), "r"(b1));
}
__device__ __forceinline__ uint32_t b2u(bf162 v) {
    union { bf162 b; uint32_t u; } c; c.b = v; return c.u;
}
// pack (a,b) to bf16x2 hi, residual to lo
__device__ __forceinline__ uint32_t packpair(float a, float b, uint32_t& lo) {
    bf162 h = __floats2bfloat162_rn(a, b);
    float2 f = __bfloat1622float2(h);
    lo = b2u(__floats2bfloat162_rn(a - f.x, b - f.y));
    return b2u(h);
}

// ---------------- bias precompute ----------------
__global__ void bias_precompute_kernel(const float* __restrict__ table) {
    int idx = blockIdx.x * blockDim.x + threadIdx.x;
    if (idx >= 4096) return;
    int delta = idx - 2047;
    int bucket = (delta > 0) ? 16 : 0;
    int rp = delta < 0 ? -delta : delta;
    int add;
    if (rp < 8) add = rp;
    else {
        float v = logf((float)rp / 8.0f) / logf(16.0f) * 8.0f;
        int vi = 8 + (int)v;
        add = vi < 15 ? vi : 15;
    }
    bucket += add;
    #pragma unroll
    for (int h = 0; h < HH; h++)
        g_bd[h*4096 + idx] = table[bucket*HH + h];
}

__global__ void bias_out_kernel(float* __restrict__ out) {
    long long i4 = (long long)blockIdx.x * blockDim.x + threadIdx.x;
    const long long per_h = (long long)SS * SS / 4;
    int h = (int)(i4 / per_h);
    long long rem = i4 - (long long)h * per_h;
    int q = (int)(rem / (SS/4));
    int k4 = (int)(rem % (SS/4)) * 4;
    const float* row = g_bd + h*4096 + (k4 - q + 2047);
    reinterpret_cast<float4*>(out)[i4] = make_float4(row[0], row[1], row[2], row[3]);
}

// ---------------- fp32 -> bf16 hi/lo split (hidden) ----------------
__global__ void split_kernel(const float* __restrict__ X,
                             bf16* __restrict__ Hi, bf16* __restrict__ Lo, int n4) {
    int i = blockIdx.x * blockDim.x + threadIdx.x;
    if (i >= n4) return;
    float4 v = reinterpret_cast<const float4*>(X)[i];
    float xs[4] = {v.x, v.y, v.z, v.w};
    ushort4 ho, lo;
    unsigned short* hp = &ho.x;
    unsigned short* lp = &lo.x;
    #pragma unroll
    for (int j = 0; j < 4; j++) {
        bf16 h = __float2bfloat16(xs[j]);
        float hf = __bfloat162float(h);
        bf16 l = __float2bfloat16(xs[j] - hf);
        hp[j] = __bfloat16_as_ushort(h);
        lp[j] = __bfloat16_as_ushort(l);
    }
    reinterpret_cast<ushort4*>(Hi)[i] = ho;
    reinterpret_cast<ushort4*>(Lo)[i] = lo;
}

// ---------------- W transpose + split: Wt[n][k] = split(W[k][n]) ----------------
__global__ void wsplit_kernel(const float* __restrict__ W,
                              bf16* __restrict__ Thi, bf16* __restrict__ Tlo) {
    __shared__ float ts[32][33];
    int bx = blockIdx.x * 32, by = blockIdx.y * 32;
    int tx = threadIdx.x, ty = threadIdx.y;
    #pragma unroll
    for (int j = 0; j < 32; j += 8)
        ts[ty + j][tx] = W[(size_t)(by + ty + j) * 1024 + bx + tx];
    __syncthreads();
    #pragma unroll
    for (int j = 0; j < 32; j += 8) {
        int n = bx + ty + j, k = by + tx;
        float x = ts[tx][ty + j];
        bf16 h = __float2bfloat16(x);
        float hf = __bfloat162float(h);
        bf16 l = __float2bfloat16(x - hf);
        Thi[(size_t)n * 1024 + k] = h;
        Tlo[(size_t)n * 1024 + k] = l;
    }
}

// ---------------- mma.sync GEMM: C[4096,1024] = A @ Wt^T, 3-pass bf16 ----------------
// CTA 128x128, 8 warps (2x4), warp tile 64x32. k-chunk 32, cp.async double buffer.
// smem tile pitch 40 bf16 elems (80B). Tile = 128*40*2 = 10240 B. 4 tiles/buf.
#define GT 10240
#define GBUF 40960
#define GEMM_SMEM (2*GBUF)

__global__ __launch_bounds__(256) void gemm_mma_kernel(
    const bf16* __restrict__ Ahi, const bf16* __restrict__ Alo,
    const bf16* __restrict__ Bhi, const bf16* __restrict__ Blo,
    float* __restrict__ Cf, bf16* __restrict__ Chi, bf16* __restrict__ Clo,
    int wantf32)
{
    extern __shared__ char smem[];
    uint32_t sb = smem_u32(smem);
    int tid = threadIdx.x, w = tid >> 5, lane = tid & 31;
    int g = lane >> 2, t2 = (lane & 3) * 2;
    int wm = w >> 2, wn = w & 3;
    int m0 = blockIdx.y * 128, n0 = blockIdx.x * 128;

    float c[4][4][4];
    #pragma unroll
    for (int i = 0; i < 4; i++)
        #pragma unroll
        for (int j = 0; j < 4; j++)
            #pragma unroll
            for (int r = 0; r < 4; r++) c[i][j][r] = 0.f;

    auto load_chunk = [&](int ch, int buf) {
        int k0 = ch * 32;
        uint32_t base = sb + (uint32_t)buf * GBUF;
        #pragma unroll
        for (int t = 0; t < 2; t++) {
            int idx = tid + t * 256;
            int row = idx >> 2, seg = idx & 3;
            uint32_t doff = (uint32_t)(row * 40 + seg * 8) * 2;
            size_t aoff = (size_t)(m0 + row) * 1024 + k0 + seg * 8;
            size_t boff = (size_t)(n0 + row) * 1024 + k0 + seg * 8;
            cp16(base + doff,          Ahi + aoff);
            cp16(base + GT + doff,     Alo + aoff);
            cp16(base + 2*GT + doff,   Bhi + boff);
            cp16(base + 3*GT + doff,   Blo + boff);
        }
    };

    load_chunk(0, 0); CP_COMMIT();
    for (int ch = 0; ch < 32; ch++) {
        int buf = ch & 1;
        if (ch + 1 < 32) { load_chunk(ch + 1, buf ^ 1); CP_COMMIT(); CP_WAIT(1); }
        else CP_WAIT(0);
        __syncthreads();
        uint32_t base = sb + (uint32_t)buf * GBUF;
        #pragma unroll
        for (int ks = 0; ks < 2; ks++) {
            uint32_t ah[4][4], al[4][4];
            #pragma unroll
            for (int mt = 0; mt < 4; mt++) {
                uint32_t ab = base + (uint32_t)((wm*64 + mt*16 + g)*40 + ks*16 + t2)*2;
                ah[mt][0] = lds32(ab);       ah[mt][1] = lds32(ab + 640);
                ah[mt][2] = lds32(ab + 16);  ah[mt][3] = lds32(ab + 656);
                uint32_t lb = ab + GT;
                al[mt][0] = lds32(lb);       al[mt][1] = lds32(lb + 640);
                al[mt][2] = lds32(lb + 16);  al[mt][3] = lds32(lb + 656);
            }
            #pragma unroll
            for (int nt = 0; nt < 4; nt++) {
                uint32_t bb = base + 2*GT + (uint32_t)((wn*32 + nt*8 + g)*40 + ks*16 + t2)*2;
                uint32_t bh0 = lds32(bb), bh1 = lds32(bb + 16);
                uint32_t bl0 = lds32(bb + GT), bl1 = lds32(bb + GT + 16);
                #pragma unroll
                for (int mt = 0; mt < 4; mt++) {
                    mma16816(c[mt][nt], ah[mt], bh0, bh1);
                    mma16816(c[mt][nt], ah[mt], bl0, bl1);
                    mma16816(c[mt][nt], al[mt], bh0, bh1);
                }
            }
        }
        __syncthreads();
    }

    #pragma unroll
    for (int mt = 0; mt < 4; mt++) {
        #pragma unroll
        for (int nt = 0; nt < 4; nt++) {
            int m = m0 + wm*64 + mt*16 + g;
            int n = n0 + wn*32 + nt*8 + t2;
            float* cr = c[mt][nt];
            if (wantf32) {
                *reinterpret_cast<float2*>(&Cf[(size_t)m*1024 + n])     = make_float2(cr[0], cr[1]);
                *reinterpret_cast<float2*>(&Cf[(size_t)(m+8)*1024 + n]) = make_float2(cr[2], cr[3]);
            } else {
                uint32_t lo0, lo1;
                uint32_t h0 = packpair(cr[0], cr[1], lo0);
                uint32_t h1 = packpair(cr[2], cr[3], lo1);
                *reinterpret_cast<uint32_t*>(&Chi[(size_t)m*1024 + n])     = h0;
                *reinterpret_cast<uint32_t*>(&Clo[(size_t)m*1024 + n])     = lo0;
                *reinterpret_cast<uint32_t*>(&Chi[(size_t)(m+8)*1024 + n]) = h1;
                *reinterpret_cast<uint32_t*>(&Clo[(size_t)(m+8)*1024 + n]) = lo1;
            }
        }
    }
}

// ---------------- flash attention with mma.sync ----------------
// CTA: (qtile 128 rows, bh). 8 warps x 16 q-rows. Key tiles of 128.
// smem (bytes): Qhi 0 (18432=128*72*2), Qlo 18432, Khi 36864, Klo 55296,
//               Vthi 73728 (16896=64*132*2), Vtlo 90624, sbias 107520 (8704)
#define SQHI 0
#define SQLO 18432
#define SKHI 36864
#define SKLO 55296
#define SVTHI 73728
#define SVTLO 90624
#define SBIAS 107520
#define FL_SMEM (SBIAS + 8704)

__global__ __launch_bounds__(256) void flash_mma_kernel() {
    extern __shared__ char smem[];
    uint32_t sb = smem_u32(smem);
    float* sbias = reinterpret_cast<float*>(smem + SBIAS);

    int tid = threadIdx.x, w = tid >> 5, lane = tid & 31;
    int g = lane >> 2, t2 = (lane & 3) * 2;
    int q0 = blockIdx.x * 128;
    int bh = blockIdx.y;
    int h = bh & 15, b = bh >> 4;
    int hbase = h * 64;
    size_t qrow0 = (size_t)(b * SS + q0);

    // Q tiles via cp.async (128 rows x 64 cols bf16, pitch 72)
    #pragma unroll
    for (int t = 0; t < 4; t++) {
        int idx = tid + t * 256;
        int row = idx >> 3, seg = idx & 7;
        uint32_t doff = (uint32_t)(row * 72 + seg * 8) * 2;
        size_t goff = (qrow0 + row) * 1024 + hbase + seg * 8;
        cp16(sb + SQHI + doff, g_Qhi + goff);
        cp16(sb + SQLO + doff, g_Qlo + goff);
    }
    CP_COMMIT();
    // bias window
    for (int i = tid; i < 2176; i += 256) {
        int gidx = (1920 - q0) + i;
        float v = 0.f;
        if (gidx >= 0 && gidx < 4096) v = g_bd[h*4096 + gidx];
        sbias[i] = v;
    }

    float acc[8][4];
    #pragma unroll
    for (int i = 0; i < 8; i++)
        #pragma unroll
        for (int r = 0; r < 4; r++) acc[i][r] = 0.f;
    float mrow[2] = {-1e30f, -1e30f};
    float lrow[2] = {0.f, 0.f};

    for (int kt = 0; kt < 16; kt++) {
        __syncthreads();   // prior compute done with K/V smem
        int kb = kt * 128;
        size_t krow0 = (size_t)(b * SS + kb);
        // K tiles via cp.async
        #pragma unroll
        for (int t = 0; t < 4; t++) {
            int idx = tid + t * 256;
            int row = idx >> 3, seg = idx & 7;
            uint32_t doff = (uint32_t)(row * 72 + seg * 8) * 2;
            size_t goff = (krow0 + row) * 1024 + hbase + seg * 8;
            cp16(sb + SKHI + doff, g_Khi + goff);
            cp16(sb + SKLO + doff, g_Klo + goff);
        }
        CP_COMMIT();
        // V transpose into Vt[d][k] pitch 132
        #pragma unroll
        for (int t = 0; t < 8; t++) {
            int idx = tid + t * 256;
            int kr = idx & 127;
            int c4 = (idx >> 7) * 4;
            size_t goff = (krow0 + kr) * 1024 + hbase + c4;
            uint2 uh = *reinterpret_cast<const uint2*>(g_Vhi + goff);
            uint2 ul = *reinterpret_cast<const uint2*>(g_Vlo + goff);
            unsigned short hs[4] = {(unsigned short)(uh.x & 0xffff), (unsigned short)(uh.x >> 16),
                                    (unsigned short)(uh.y & 0xffff), (unsigned short)(uh.y >> 16)};
            unsigned short ls[4] = {(unsigned short)(ul.x & 0xffff), (unsigned short)(ul.x >> 16),
                                    (unsigned short)(ul.y & 0xffff), (unsigned short)(ul.y >> 16)};
            #pragma unroll
            for (int j = 0; j < 4; j++) {
                uint32_t off = (uint32_t)((c4 + j) * 132 + kr) * 2;
                sts16(sb + SVTHI + off, hs[j]);
                sts16(sb + SVTLO + off, ls[j]);
            }
        }
        CP_WAIT(0);
        __syncthreads();

        // ---- scores: s[j] covers k-cols [kb + j*8, kb + j*8 + 8) ----
        float s[16][4];
        #pragma unroll
        for (int j = 0; j < 16; j++)
            #pragma unroll
            for (int r = 0; r < 4; r++) s[j][r] = 0.f;

        #pragma unroll
        for (int ks = 0; ks < 4; ks++) {
            uint32_t qb = sb + SQHI + (uint32_t)((w*16 + g)*72 + ks*16 + t2)*2;
            uint32_t qh[4], ql[4];
            qh[0] = lds32(qb);          qh[1] = lds32(qb + 1152);
            qh[2] = lds32(qb + 16);     qh[3] = lds32(qb + 1168);
            uint32_t qlb = qb + (SQLO - SQHI);
            ql[0] = lds32(qlb);         ql[1] = lds32(qlb + 1152);
            ql[2] = lds32(qlb + 16);    ql[3] = lds32(qlb + 1168);
            #pragma unroll
            for (int j = 0; j < 16; j++) {
                uint32_t kbr = sb + SKHI + (uint32_t)((j*8 + g)*72 + ks*16 + t2)*2;
                uint32_t kh0 = lds32(kbr), kh1 = lds32(kbr + 16);
                uint32_t kl0 = lds32(kbr + (SKLO - SKHI)), kl1 = lds32(kbr + (SKLO - SKHI) + 16);
                mma16816(s[j], qh, kh0, kh1);
                mma16816(s[j], qh, kl0, kl1);
                mma16816(s[j], ql, kh0, kh1);
            }
        }

        // ---- bias + online softmax ----
        int qrel0 = w*16 + g;
        #pragma unroll
        for (int j = 0; j < 16; j++) {
            int idx0 = kb + j*8 + t2 - qrel0 + 127;
            s[j][0] += sbias[idx0];
            s[j][1] += sbias[idx0 + 1];
            s[j][2] += sbias[idx0 - 8];
            s[j][3] += sbias[idx0 - 7];
        }
        float mx0 = -1e30f, mx1 = -1e30f;
        #pragma unroll
        for (int j = 0; j < 16; j++) {
            mx0 = fmaxf(mx0, fmaxf(s[j][0], s[j][1]));
            mx1 = fmaxf(mx1, fmaxf(s[j][2], s[j][3]));
        }
        mx0 = fmaxf(mx0, __shfl_xor_sync(0xffffffffu, mx0, 1));
        mx0 = fmaxf(mx0, __shfl_xor_sync(0xffffffffu, mx0, 2));
        mx1 = fmaxf(mx1, __shfl_xor_sync(0xffffffffu, mx1, 1));
        mx1 = fmaxf(mx1, __shfl_xor_sync(0xffffffffu, mx1, 2));
        float mn0 = fmaxf(mrow[0], mx0), mn1 = fmaxf(mrow[1], mx1);
        float f0 = __expf(mrow[0] - mn0), f1 = __expf(mrow[1] - mn1);
        float sum0 = 0.f, sum1 = 0.f;
        #pragma unroll
        for (int j = 0; j < 16; j++) {
            s[j][0] = __expf(s[j][0] - mn0);
            s[j][1] = __expf(s[j][1] - mn0);
            s[j][2] = __expf(s[j][2] - mn1);
            s[j][3] = __expf(s[j][3] - mn1);
            sum0 += s[j][0] + s[j][1];
            sum1 += s[j][2] + s[j][3];
        }
        sum0 += __shfl_xor_sync(0xffffffffu, sum0, 1);
        sum0 += __shfl_xor_sync(0xffffffffu, sum0, 2);
        sum1 += __shfl_xor_sync(0xffffffffu, sum1, 1);
        sum1 += __shfl_xor_sync(0xffffffffu, sum1, 2);
        lrow[0] = lrow[0]*f0 + sum0;
        lrow[1] = lrow[1]*f1 + sum1;
        mrow[0] = mn0; mrow[1] = mn1;
        #pragma unroll
        for (int jn = 0; jn < 8; jn++) {
            acc[jn][0] *= f0; acc[jn][1] *= f0;
            acc[jn][2] *= f1; acc[jn][3] *= f1;
        }

        // ---- PV: acc += P @ V ----
        #pragma unroll
        for (int kk = 0; kk < 8; kk++) {
            int j0 = 2*kk, j1 = 2*kk + 1;
            uint32_t ph[4], pl[4];
            ph[0] = packpair(s[j0][0], s[j0][1], pl[0]);
            ph[1] = packpair(s[j0][2], s[j0][3], pl[1]);
            ph[2] = packpair(s[j1][0], s[j1][1], pl[2]);
            ph[3] = packpair(s[j1][2], s[j1][3], pl[3]);
            #pragma unroll
            for (int jn = 0; jn < 8; jn++) {
                uint32_t vb = sb + SVTHI + (uint32_t)((jn*8 + g)*132 + kk*16 + t2)*2;
                uint32_t vh0 = lds32(vb), vh1 = lds32(vb + 16);
                uint32_t vl0 = lds32(vb + (SVTLO - SVTHI)), vl1 = lds32(vb + (SVTLO - SVTHI) + 16);
                mma16816(acc[jn], ph, vh0, vh1);
                mma16816(acc[jn], ph, vl0, vl1);
                mma16816(acc[jn], pl, vh0, vh1);
            }
        }
    }

    // ---- epilogue: ctx hi/lo ----
    float i0 = 1.0f / lrow[0], i1 = 1.0f / lrow[1];
    size_t r0 = qrow0 + w*16 + g;
    #pragma unroll
    for (int jn = 0; jn < 8; jn++) {
        int n = hbase + jn*8 + t2;
        uint32_t lo0, lo1;
        uint32_t h0 = packpair(acc[jn][0]*i0, acc[jn][1]*i0, lo0);
        uint32_t h1 = packpair(acc[jn][2]*i1, acc[jn][3]*i1, lo1);
        *reinterpret_cast<uint32_t*>(&g_chi[r0*1024 + n])       = h0;
        *reinterpret_cast<uint32_t*>(&g_clo[r0*1024 + n])       = lo0;
        *reinterpret_cast<uint32_t*>(&g_chi[(r0+8)*1024 + n])   = h1;
        *reinterpret_cast<uint32_t*>(&g_clo[(r0+8)*1024 + n])   = lo1;
    }
}

// ---------------- launch ----------------
extern "C" void kernel_launch(void* const* d_in, const int* in_sizes, int n_in,
                              void* d_out, int out_size)
{
    const float* hidden = (const float*)d_in[0];
    const float* Wq     = (const float*)d_in[1];
    const float* Wk     = (const float*)d_in[2];
    const float* Wv     = (const float*)d_in[3];
    const float* Wo     = (const float*)d_in[4];
    const float* tbl    = (const float*)d_in[5];
    float* out = (float*)d_out;
    (void)in_sizes; (void)n_in;

    bf16 *phhi, *phlo, *pWthi, *pWtlo, *pQhi, *pQlo, *pKhi, *pKlo, *pVhi, *pVlo, *pchi, *pclo;
    cudaGetSymbolAddress((void**)&phhi, g_hhi);
    cudaGetSymbolAddress((void**)&phlo, g_hlo);
    cudaGetSymbolAddress((void**)&pWthi, g_Wthi);
    cudaGetSymbolAddress((void**)&pWtlo, g_Wtlo);
    cudaGetSymbolAddress((void**)&pQhi, g_Qhi);
    cudaGetSymbolAddress((void**)&pQlo, g_Qlo);
    cudaGetSymbolAddress((void**)&pKhi, g_Khi);
    cudaGetSymbolAddress((void**)&pKlo, g_Klo);
    cudaGetSymbolAddress((void**)&pVhi, g_Vhi);
    cudaGetSymbolAddress((void**)&pVlo, g_Vlo);
    cudaGetSymbolAddress((void**)&pchi, g_chi);
    cudaGetSymbolAddress((void**)&pclo, g_clo);

    cudaFuncSetAttribute(gemm_mma_kernel,
                         cudaFuncAttributeMaxDynamicSharedMemorySize, GEMM_SMEM);
    cudaFuncSetAttribute(flash_mma_kernel,
                         cudaFuncAttributeMaxDynamicSharedMemorySize, FL_SMEM);

    const size_t WSLOT = (size_t)DDIM * DDIM;

    // 1. bias table + input splits + weight transpose/splits
    bias_precompute_kernel<<<16, 256>>>(tbl);
    int n4 = MROWS * DDIM / 4;
    split_kernel<<<(n4 + 255) / 256, 256>>>(hidden, phhi, phlo, n4);
    dim3 wgrid(32, 32), wblock(32, 8);
    wsplit_kernel<<<wgrid, wblock>>>(Wq, pWthi + 0*WSLOT, pWtlo + 0*WSLOT);
    wsplit_kernel<<<wgrid, wblock>>>(Wk, pWthi + 1*WSLOT, pWtlo + 1*WSLOT);
    wsplit_kernel<<<wgrid, wblock>>>(Wv, pWthi + 2*WSLOT, pWtlo + 2*WSLOT);
    wsplit_kernel<<<wgrid, wblock>>>(Wo, pWthi + 3*WSLOT, pWtlo + 3*WSLOT);

    // 2. Q/K/V projections -> bf16 hi/lo
    dim3 ggrid(8, 32);
    gemm_mma_kernel<<<ggrid, 256, GEMM_SMEM>>>(phhi, phlo, pWthi + 0*WSLOT, pWtlo + 0*WSLOT,
                                               nullptr, pQhi, pQlo, 0);
    gemm_mma_kernel<<<ggrid, 256, GEMM_SMEM>>>(phhi, phlo, pWthi + 1*WSLOT, pWtlo + 1*WSLOT,
                                               nullptr, pKhi, pKlo, 0);
    gemm_mma_kernel<<<ggrid, 256, GEMM_SMEM>>>(phhi, phlo, pWthi + 2*WSLOT, pWtlo + 2*WSLOT,
                                               nullptr, pVhi, pVlo, 0);

    // 3. flash attention -> ctx hi/lo
    dim3 fgrid(SS/128, BB*HH);
    flash_mma_kernel<<<fgrid, 256, FL_SMEM>>>();

    // 4. output projection -> fp32 out
    gemm_mma_kernel<<<ggrid, 256, GEMM_SMEM>>>(pchi, pclo, pWthi + 3*WSLOT, pWtlo + 3*WSLOT,
                                               out, nullptr, nullptr, 1);

    // 5. position_bias
    long long attn_elems = (long long)MROWS * DDIM;
    long long bias_elems = (long long)HH * SS * SS;
    if ((long long)out_size >= attn_elems + bias_elems) {
        int nblocks = (int)(bias_elems / 4 / 256);
        bias_out_kernel<<<nblocks, 256>>>(out + attn_elems);
    }
}

// round 7
// speedup vs baseline: 2.2869x; 1.1063x over previous
#include <cuda_runtime.h>
#include <cuda_fp16.h>
#include <math.h>
#include <stdint.h>

#define BB 2
#define SS 2048
#define DDIM 1024
#define HH 16
#define DK 64
#define MROWS 4096   // B*S

typedef __half h16;

// ---------------- device scratch ----------------
__device__ __align__(16) h16 g_hhi[MROWS*DDIM];
__device__ __align__(16) h16 g_hlo[MROWS*DDIM];
__device__ __align__(16) h16 g_Wthi[4*DDIM*DDIM];   // [slot][n][k]
__device__ __align__(16) h16 g_Wtlo[4*DDIM*DDIM];
__device__ __align__(16) h16 g_Qhi[MROWS*DDIM];
__device__ __align__(16) h16 g_Qlo[MROWS*DDIM];
__device__ __align__(16) h16 g_Khi[MROWS*DDIM];
__device__ __align__(16) h16 g_Klo[MROWS*DDIM];
__device__ __align__(16) h16 g_Vhi[MROWS*DDIM];
__device__ __align__(16) h16 g_Vlo[MROWS*DDIM];
__device__ __align__(16) h16 g_chi[MROWS*DDIM];
__device__ __align__(16) h16 g_clo[MROWS*DDIM];
__device__ __align__(16) float g_bd[HH*4096];

// ---------------- low-level helpers ----------------
__device__ __forceinline__ uint32_t smem_u32(const void* p) {
    uint32_t a;
    asm("{ .reg .u64 t; cvta.to.shared.u64 t, %1; cvt.u32.u64 %0, t; }" : "=r"(a) : "l"(p));
    return a;
}
__device__ __forceinline__ void sts16(uint32_t a, unsigned short v) {
    asm volatile("st.shared.u16 [%0], %1;" :: "r"(a), "h"(v));
}
__device__ __forceinline__ void cp16(uint32_t dst, const void* src) {
    asm volatile("cp.async.ca.shared.global [%0], [%1], 16;" :: "r"(dst), "l"(src));
}
#define CP_COMMIT() asm volatile("cp.async.commit_group;" ::: "memory")
#define CP_WAIT(N)  asm volatile("cp.async.wait_group %0;" :: "n"(N) : "memory")

__device__ __forceinline__ void ldsm4(uint32_t* r, uint32_t addr) {
    asm volatile("ldmatrix.sync.aligned.m8n8.x4.shared.b16 {%0,%1,%2,%3}, [%4];"
        : "=r"(r[0]), "=r"(r[1]), "=r"(r[2]), "=r"(r[3]) : "r"(addr));
}
__device__ __forceinline__ void mma_f16(float* c, const uint32_t* a, uint32_t b0, uint32_t b1) {
    asm volatile("mma.sync.aligned.m16n8k16.row.col.f32.f16.f16.f32 "
        "{%0,%1,%2,%3}, {%4,%5,%6,%7}, {%8,%9}, {%0,%1,%2,%3};"
        : "+f"(c[0]), "+f"(c[1]), "+f"(c[2]), "+f"(c[3])
        : "r"(a[0]), "r"(a[1]), "r"(a[2]), "r"(a[3]), "r"(b0), "r"(b1));
}
__device__ __forceinline__ uint32_t h2u(__half2 v) {
    union { __half2 h; uint32_t u; } c; c.h = v; return c.u;
}
// pack (a,b) to fp16x2 hi, residual to lo
__device__ __forceinline__ uint32_t packpair(float a, float b, uint32_t& lo) {
    __half2 h = __floats2half2_rn(a, b);
    float2 f = __half22float2(h);
    lo = h2u(__floats2half2_rn(a - f.x, b - f.y));
    return h2u(h);
}

// ---------------- bias precompute ----------------
__global__ void bias_precompute_kernel(const float* __restrict__ table) {
    int idx = blockIdx.x * blockDim.x + threadIdx.x;
    if (idx >= 4096) return;
    int delta = idx - 2047;
    int bucket = (delta > 0) ? 16 : 0;
    int rp = delta < 0 ? -delta : delta;
    int add;
    if (rp < 8) add = rp;
    else {
        float v = logf((float)rp / 8.0f) / logf(16.0f) * 8.0f;
        int vi = 8 + (int)v;
        add = vi < 15 ? vi : 15;
    }
    bucket += add;
    #pragma unroll
    for (int h = 0; h < HH; h++)
        g_bd[h*4096 + idx] = table[bucket*HH + h];
}

__global__ void bias_out_kernel(float* __restrict__ out) {
    long long i4 = (long long)blockIdx.x * blockDim.x + threadIdx.x;
    const long long per_h = (long long)SS * SS / 4;
    int h = (int)(i4 / per_h);
    long long rem = i4 - (long long)h * per_h;
    int q = (int)(rem / (SS/4));
    int k4 = (int)(rem % (SS/4)) * 4;
    const float* row = g_bd + h*4096 + (k4 - q + 2047);
    reinterpret_cast<float4*>(out)[i4] = make_float4(row[0], row[1], row[2], row[3]);
}

// ---------------- fp32 -> fp16 hi/lo split (hidden) ----------------
__global__ void split_kernel(const float* __restrict__ X,
                             h16* __restrict__ Hi, h16* __restrict__ Lo, int n4) {
    int i = blockIdx.x * blockDim.x + threadIdx.x;
    if (i >= n4) return;
    float4 v = reinterpret_cast<const float4*>(X)[i];
    float xs[4] = {v.x, v.y, v.z, v.w};
    ushort4 ho, lo;
    unsigned short* hp = &ho.x;
    unsigned short* lp = &lo.x;
    #pragma unroll
    for (int j = 0; j < 4; j++) {
        h16 h = __float2half_rn(xs[j]);
        float hf = __half2float(h);
        h16 l = __float2half_rn(xs[j] - hf);
        hp[j] = __half_as_ushort(h);
        lp[j] = __half_as_ushort(l);
    }
    reinterpret_cast<ushort4*>(Hi)[i] = ho;
    reinterpret_cast<ushort4*>(Lo)[i] = lo;
}

// ---------------- fused W transpose + split (z = slot 0..3) ----------------
__global__ void wsplit4_kernel(const float* __restrict__ W0, const float* __restrict__ W1,
                               const float* __restrict__ W2, const float* __restrict__ W3,
                               h16* __restrict__ ThiB, h16* __restrict__ TloB) {
    __shared__ float ts[32][33];
    int z = blockIdx.z;
    const float* W = (z == 0) ? W0 : (z == 1) ? W1 : (z == 2) ? W2 : W3;
    h16* Thi = ThiB + (size_t)z * DDIM * DDIM;
    h16* Tlo = TloB + (size_t)z * DDIM * DDIM;
    int bx = blockIdx.x * 32, by = blockIdx.y * 32;
    int tx = threadIdx.x, ty = threadIdx.y;
    #pragma unroll
    for (int j = 0; j < 32; j += 8)
        ts[ty + j][tx] = W[(size_t)(by + ty + j) * 1024 + bx + tx];
    __syncthreads();
    #pragma unroll
    for (int j = 0; j < 32; j += 8) {
        int n = bx + ty + j, k = by + tx;
        float x = ts[tx][ty + j];
        h16 h = __float2half_rn(x);
        float hf = __half2float(h);
        h16 l = __float2half_rn(x - hf);
        Thi[(size_t)n * 1024 + k] = h;
        Tlo[(size_t)n * 1024 + k] = l;
    }
}

// ---------------- mma.sync GEMM, 3-pass fp16, fused over z (QKV) ----------------
// CTA 128x128, 8 warps (2x4), warp tile 64x32. k-chunk 32, cp.async double buffer.
// smem pitch 40 h16 (80B). Tile = 128*40*2 = 10240 B. 4 tiles/buf.
#define GT 10240
#define GBUF 40960
#define GEMM_SMEM (2*GBUF)

__global__ __launch_bounds__(256) void gemm_mma_kernel(
    const h16* __restrict__ Ahi, const h16* __restrict__ Alo,
    const h16* __restrict__ WhiB, const h16* __restrict__ WloB,
    h16* __restrict__ o0h, h16* __restrict__ o0l,
    h16* __restrict__ o1h, h16* __restrict__ o1l,
    h16* __restrict__ o2h, h16* __restrict__ o2l,
    float* __restrict__ Cf, int wantf32)
{
    extern __shared__ char smem[];
    uint32_t sb = smem_u32(smem);
    int tid = threadIdx.x, w = tid >> 5, lane = tid & 31;
    int g = lane >> 2, t2 = (lane & 3) * 2;
    int wm = w >> 2, wn = w & 3;
    int m0 = blockIdx.y * 128, n0 = blockIdx.x * 128;
    int z = blockIdx.z;
    const h16* Bhi = WhiB + (size_t)z * DDIM * DDIM;
    const h16* Blo = WloB + (size_t)z * DDIM * DDIM;
    h16* Chi = (z == 0) ? o0h : (z == 1) ? o1h : o2h;
    h16* Clo = (z == 0) ? o0l : (z == 1) ? o1l : o2l;

    // ldmatrix lane address components
    int lm_a  = lane & 15;
    int lm_ak = ((lane >> 4) & 1) * 8;
    int lm_bn = ((lane >> 4) & 1) * 8 + (lane & 7);
    int lm_bk = ((lane >> 3) & 1) * 8;

    float c[4][4][4];
    #pragma unroll
    for (int i = 0; i < 4; i++)
        #pragma unroll
        for (int j = 0; j < 4; j++)
            #pragma unroll
            for (int r = 0; r < 4; r++) c[i][j][r] = 0.f;

    auto load_chunk = [&](int ch, int buf) {
        int k0 = ch * 32;
        uint32_t base = sb + (uint32_t)buf * GBUF;
        #pragma unroll
        for (int t = 0; t < 2; t++) {
            int idx = tid + t * 256;
            int row = idx >> 2, seg = idx & 3;
            uint32_t doff = (uint32_t)(row * 40 + seg * 8) * 2;
            size_t aoff = (size_t)(m0 + row) * 1024 + k0 + seg * 8;
            size_t boff = (size_t)(n0 + row) * 1024 + k0 + seg * 8;
            cp16(base + doff,          Ahi + aoff);
            cp16(base + GT + doff,     Alo + aoff);
            cp16(base + 2*GT + doff,   Bhi + boff);
            cp16(base + 3*GT + doff,   Blo + boff);
        }
    };

    load_chunk(0, 0); CP_COMMIT();
    for (int ch = 0; ch < 32; ch++) {
        int buf = ch & 1;
        if (ch + 1 < 32) { load_chunk(ch + 1, buf ^ 1); CP_COMMIT(); CP_WAIT(1); }
        else CP_WAIT(0);
        __syncthreads();
        uint32_t base = sb + (uint32_t)buf * GBUF;
        #pragma unroll
        for (int ks = 0; ks < 2; ks++) {
            uint32_t ah[4][4], al[4][4];
            #pragma unroll
            for (int mt = 0; mt < 4; mt++) {
                uint32_t ab = base + (uint32_t)((wm*64 + mt*16 + lm_a)*40 + ks*16 + lm_ak)*2;
                ldsm4(ah[mt], ab);
                ldsm4(al[mt], ab + GT);
            }
            uint32_t bh[2][4], bl[2][4];
            #pragma unroll
            for (int np = 0; np < 2; np++) {
                uint32_t bb = base + 2*GT +
                    (uint32_t)((wn*32 + np*16 + lm_bn)*40 + ks*16 + lm_bk)*2;
                ldsm4(bh[np], bb);
                ldsm4(bl[np], bb + GT);
            }
            #pragma unroll
            for (int nt = 0; nt < 4; nt++) {
                uint32_t bh0 = bh[nt>>1][(nt&1)*2], bh1 = bh[nt>>1][(nt&1)*2+1];
                uint32_t bl0 = bl[nt>>1][(nt&1)*2], bl1 = bl[nt>>1][(nt&1)*2+1];
                #pragma unroll
                for (int mt = 0; mt < 4; mt++) {
                    mma_f16(c[mt][nt], ah[mt], bh0, bh1);
                    mma_f16(c[mt][nt], ah[mt], bl0, bl1);
                    mma_f16(c[mt][nt], al[mt], bh0, bh1);
                }
            }
        }
        __syncthreads();
    }

    #pragma unroll
    for (int mt = 0; mt < 4; mt++) {
        #pragma unroll
        for (int nt = 0; nt < 4; nt++) {
            int m = m0 + wm*64 + mt*16 + g;
            int n = n0 + wn*32 + nt*8 + t2;
            float* cr = c[mt][nt];
            if (wantf32) {
                *reinterpret_cast<float2*>(&Cf[(size_t)m*1024 + n])     = make_float2(cr[0], cr[1]);
                *reinterpret_cast<float2*>(&Cf[(size_t)(m+8)*1024 + n]) = make_float2(cr[2], cr[3]);
            } else {
                uint32_t lo0, lo1;
                uint32_t h0 = packpair(cr[0], cr[1], lo0);
                uint32_t h1 = packpair(cr[2], cr[3], lo1);
                *reinterpret_cast<uint32_t*>(&Chi[(size_t)m*1024 + n])     = h0;
                *reinterpret_cast<uint32_t*>(&Clo[(size_t)m*1024 + n])     = lo0;
                *reinterpret_cast<uint32_t*>(&Chi[(size_t)(m+8)*1024 + n]) = h1;
                *reinterpret_cast<uint32_t*>(&Clo[(size_t)(m+8)*1024 + n]) = lo1;
            }
        }
    }
}

// ---------------- flash attention with mma.sync + ldmatrix ----------------
// smem: Qhi 0 (18432=128*72*2), Qlo 18432, Khi 36864, Klo 55296,
//       Vthi 73728 (17408=64*136*2), Vtlo 91136, sbias 108544 (8704)
#define SQHI 0
#define SQLO 18432
#define SKHI 36864
#define SKLO 55296
#define SVTHI 73728
#define SVTLO 91136
#define SBIAS 108544
#define FL_SMEM (SBIAS + 8704)

__global__ __launch_bounds__(256) void flash_mma_kernel() {
    extern __shared__ char smem[];
    uint32_t sb = smem_u32(smem);
    float* sbias = reinterpret_cast<float*>(smem + SBIAS);

    int tid = threadIdx.x, w = tid >> 5, lane = tid & 31;
    int g = lane >> 2, t2 = (lane & 3) * 2;
    int q0 = blockIdx.x * 128;
    int bh = blockIdx.y;
    int h = bh & 15, b = bh >> 4;
    int hbase = h * 64;
    size_t qrow0 = (size_t)(b * SS + q0);

    int lm_a  = lane & 15;
    int lm_ak = ((lane >> 4) & 1) * 8;
    int lm_bn = ((lane >> 4) & 1) * 8 + (lane & 7);
    int lm_bk = ((lane >> 3) & 1) * 8;

    // Q tiles via cp.async (128 rows x 64 cols h16, pitch 72)
    #pragma unroll
    for (int t = 0; t < 4; t++) {
        int idx = tid + t * 256;
        int row = idx >> 3, seg = idx & 7;
        uint32_t doff = (uint32_t)(row * 72 + seg * 8) * 2;
        size_t goff = (qrow0 + row) * 1024 + hbase + seg * 8;
        cp16(sb + SQHI + doff, g_Qhi + goff);
        cp16(sb + SQLO + doff, g_Qlo + goff);
    }
    CP_COMMIT();
    for (int i = tid; i < 2176; i += 256) {
        int gidx = (1920 - q0) + i;
        float v = 0.f;
        if (gidx >= 0 && gidx < 4096) v = g_bd[h*4096 + gidx];
        sbias[i] = v;
    }

    float acc[8][4];
    #pragma unroll
    for (int i = 0; i < 8; i++)
        #pragma unroll
        for (int r = 0; r < 4; r++) acc[i][r] = 0.f;
    float mrow[2] = {-1e30f, -1e30f};
    float lrow[2] = {0.f, 0.f};

    for (int kt = 0; kt < 16; kt++) {
        __syncthreads();
        int kb = kt * 128;
        size_t krow0 = (size_t)(b * SS + kb);
        #pragma unroll
        for (int t = 0; t < 4; t++) {
            int idx = tid + t * 256;
            int row = idx >> 3, seg = idx & 7;
            uint32_t doff = (uint32_t)(row * 72 + seg * 8) * 2;
            size_t goff = (krow0 + row) * 1024 + hbase + seg * 8;
            cp16(sb + SKHI + doff, g_Khi + goff);
            cp16(sb + SKLO + doff, g_Klo + goff);
        }
        CP_COMMIT();
        // V transpose into Vt[d][k], pitch 136
        #pragma unroll
        for (int t = 0; t < 8; t++) {
            int idx = tid + t * 256;
            int kr = idx & 127;
            int c4 = (idx >> 7) * 4;
            size_t goff = (krow0 + kr) * 1024 + hbase + c4;
            uint2 uh = *reinterpret_cast<const uint2*>(g_Vhi + goff);
            uint2 ul = *reinterpret_cast<const uint2*>(g_Vlo + goff);
            unsigned short hs[4] = {(unsigned short)(uh.x & 0xffff), (unsigned short)(uh.x >> 16),
                                    (unsigned short)(uh.y & 0xffff), (unsigned short)(uh.y >> 16)};
            unsigned short ls[4] = {(unsigned short)(ul.x & 0xffff), (unsigned short)(ul.x >> 16),
                                    (unsigned short)(ul.y & 0xffff), (unsigned short)(ul.y >> 16)};
            #pragma unroll
            for (int j = 0; j < 4; j++) {
                uint32_t off = (uint32_t)((c4 + j) * 136 + kr) * 2;
                sts16(sb + SVTHI + off, hs[j]);
                sts16(sb + SVTLO + off, ls[j]);
            }
        }
        CP_WAIT(0);
        __syncthreads();

        // ---- scores ----
        float s[16][4];
        #pragma unroll
        for (int j = 0; j < 16; j++)
            #pragma unroll
            for (int r = 0; r < 4; r++) s[j][r] = 0.f;

        #pragma unroll
        for (int ks = 0; ks < 4; ks++) {
            uint32_t qa = sb + SQHI + (uint32_t)((w*16 + lm_a)*72 + ks*16 + lm_ak)*2;
            uint32_t qh[4], ql[4];
            ldsm4(qh, qa);
            ldsm4(ql, qa + (SQLO - SQHI));
            #pragma unroll
            for (int jp = 0; jp < 8; jp++) {
                uint32_t ka = sb + SKHI + (uint32_t)((jp*16 + lm_bn)*72 + ks*16 + lm_bk)*2;
                uint32_t kh[4], kl[4];
                ldsm4(kh, ka);
                ldsm4(kl, ka + (SKLO - SKHI));
                mma_f16(s[2*jp],   qh, kh[0], kh[1]);
                mma_f16(s[2*jp],   qh, kl[0], kl[1]);
                mma_f16(s[2*jp],   ql, kh[0], kh[1]);
                mma_f16(s[2*jp+1], qh, kh[2], kh[3]);
                mma_f16(s[2*jp+1], qh, kl[2], kl[3]);
                mma_f16(s[2*jp+1], ql, kh[2], kh[3]);
            }
        }

        // ---- bias + online softmax ----
        int qrel0 = w*16 + g;
        #pragma unroll
        for (int j = 0; j < 16; j++) {
            int idx0 = kb + j*8 + t2 - qrel0 + 127;
            s[j][0] += sbias[idx0];
            s[j][1] += sbias[idx0 + 1];
            s[j][2] += sbias[idx0 - 8];
            s[j][3] += sbias[idx0 - 7];
        }
        float mx0 = -1e30f, mx1 = -1e30f;
        #pragma unroll
        for (int j = 0; j < 16; j++) {
            mx0 = fmaxf(mx0, fmaxf(s[j][0], s[j][1]));
            mx1 = fmaxf(mx1, fmaxf(s[j][2], s[j][3]));
        }
        mx0 = fmaxf(mx0, __shfl_xor_sync(0xffffffffu, mx0, 1));
        mx0 = fmaxf(mx0, __shfl_xor_sync(0xffffffffu, mx0, 2));
        mx1 = fmaxf(mx1, __shfl_xor_sync(0xffffffffu, mx1, 1));
        mx1 = fmaxf(mx1, __shfl_xor_sync(0xffffffffu, mx1, 2));
        float mn0 = fmaxf(mrow[0], mx0), mn1 = fmaxf(mrow[1], mx1);
        float f0 = __expf(mrow[0] - mn0), f1 = __expf(mrow[1] - mn1);
        float sum0 = 0.f, sum1 = 0.f;
        #pragma unroll
        for (int j = 0; j < 16; j++) {
            s[j][0] = __expf(s[j][0] - mn0);
            s[j][1] = __expf(s[j][1] - mn0);
            s[j][2] = __expf(s[j][2] - mn1);
            s[j][3] = __expf(s[j][3] - mn1);
            sum0 += s[j][0] + s[j][1];
            sum1 += s[j][2] + s[j][3];
        }
        sum0 += __shfl_xor_sync(0xffffffffu, sum0, 1);
        sum0 += __shfl_xor_sync(0xffffffffu, sum0, 2);
        sum1 += __shfl_xor_sync(0xffffffffu, sum1, 1);
        sum1 += __shfl_xor_sync(0xffffffffu, sum1, 2);
        lrow[0] = lrow[0]*f0 + sum0;
        lrow[1] = lrow[1]*f1 + sum1;
        mrow[0] = mn0; mrow[1] = mn1;
        #pragma unroll
        for (int jn = 0; jn < 8; jn++) {
            acc[jn][0] *= f0; acc[jn][1] *= f0;
            acc[jn][2] *= f1; acc[jn][3] *= f1;
        }

        // ---- PV ----
        #pragma unroll
        for (int kk = 0; kk < 8; kk++) {
            int j0 = 2*kk, j1 = 2*kk + 1;
            uint32_t ph[4], pl[4];
            ph[0] = packpair(s[j0][0], s[j0][1], pl[0]);
            ph[1] = packpair(s[j0][2], s[j0][3], pl[1]);
            ph[2] = packpair(s[j1][0], s[j1][1], pl[2]);
            ph[3] = packpair(s[j1][2], s[j1][3], pl[3]);
            #pragma unroll
            for (int jp = 0; jp < 4; jp++) {
                uint32_t va = sb + SVTHI + (uint32_t)((jp*16 + lm_bn)*136 + kk*16 + lm_bk)*2;
                uint32_t vh[4], vl[4];
                ldsm4(vh, va);
                ldsm4(vl, va + (SVTLO - SVTHI));
                mma_f16(acc[2*jp],   ph, vh[0], vh[1]);
                mma_f16(acc[2*jp],   ph, vl[0], vl[1]);
                mma_f16(acc[2*jp],   pl, vh[0], vh[1]);
                mma_f16(acc[2*jp+1], ph, vh[2], vh[3]);
                mma_f16(acc[2*jp+1], ph, vl[2], vl[3]);
                mma_f16(acc[2*jp+1], pl, vh[2], vh[3]);
            }
        }
    }

    // ---- epilogue: ctx hi/lo ----
    float i0 = 1.0f / lrow[0], i1 = 1.0f / lrow[1];
    size_t r0 = qrow0 + w*16 + g;
    #pragma unroll
    for (int jn = 0; jn < 8; jn++) {
        int n = hbase + jn*8 + t2;
        uint32_t lo0, lo1;
        uint32_t h0 = packpair(acc[jn][0]*i0, acc[jn][1]*i0, lo0);
        uint32_t h1 = packpair(acc[jn][2]*i1, acc[jn][3]*i1, lo1);
        *reinterpret_cast<uint32_t*>(&g_chi[r0*1024 + n])       = h0;
        *reinterpret_cast<uint32_t*>(&g_clo[r0*1024 + n])       = lo0;
        *reinterpret_cast<uint32_t*>(&g_chi[(r0+8)*1024 + n])   = h1;
        *reinterpret_cast<uint32_t*>(&g_clo[(r0+8)*1024 + n])   = lo1;
    }
}

// ---------------- launch ----------------
extern "C" void kernel_launch(void* const* d_in, const int* in_sizes, int n_in,
                              void* d_out, int out_size)
{
    const float* hidden = (const float*)d_in[0];
    const float* Wq     = (const float*)d_in[1];
    const float* Wk     = (const float*)d_in[2];
    const float* Wv     = (const float*)d_in[3];
    const float* Wo     = (const float*)d_in[4];
    const float* tbl    = (const float*)d_in[5];
    float* out = (float*)d_out;
    (void)in_sizes; (void)n_in;

    h16 *phhi, *phlo, *pWthi, *pWtlo, *pQhi, *pQlo, *pKhi, *pKlo, *pVhi, *pVlo, *pchi, *pclo;
    cudaGetSymbolAddress((void**)&phhi, g_hhi);
    cudaGetSymbolAddress((void**)&phlo, g_hlo);
    cudaGetSymbolAddress((void**)&pWthi, g_Wthi);
    cudaGetSymbolAddress((void**)&pWtlo, g_Wtlo);
    cudaGetSymbolAddress((void**)&pQhi, g_Qhi);
    cudaGetSymbolAddress((void**)&pQlo, g_Qlo);
    cudaGetSymbolAddress((void**)&pKhi, g_Khi);
    cudaGetSymbolAddress((void**)&pKlo, g_Klo);
    cudaGetSymbolAddress((void**)&pVhi, g_Vhi);
    cudaGetSymbolAddress((void**)&pVlo, g_Vlo);
    cudaGetSymbolAddress((void**)&pchi, g_chi);
    cudaGetSymbolAddress((void**)&pclo, g_clo);

    cudaFuncSetAttribute(gemm_mma_kernel,
                         cudaFuncAttributeMaxDynamicSharedMemorySize, GEMM_SMEM);
    cudaFuncSetAttribute(flash_mma_kernel,
                         cudaFuncAttributeMaxDynamicSharedMemorySize, FL_SMEM);

    const size_t WSLOT = (size_t)DDIM * DDIM;
    int n4 = MROWS * DDIM / 4;
    long long attn_elems = (long long)MROWS * DDIM;
    long long bias_elems = (long long)HH * SS * SS;

    // 1. hidden split
    split_kernel<<<(n4 + 255) / 256, 256>>>(hidden, phhi, phlo, n4);
    // 2. fused W transpose+split
    wsplit4_kernel<<<dim3(32, 32, 4), dim3(32, 8)>>>(Wq, Wk, Wv, Wo, pWthi, pWtlo);
    // 3. fused Q/K/V projections
    gemm_mma_kernel<<<dim3(8, 32, 3), 256, GEMM_SMEM>>>(
        phhi, phlo, pWthi, pWtlo,
        pQhi, pQlo, pKhi, pKlo, pVhi, pVlo, nullptr, 0);
    // 4. bias table
    bias_precompute_kernel<<<16, 256>>>(tbl);
    // 5. position_bias output
    if ((long long)out_size >= attn_elems + bias_elems) {
        int nblocks = (int)(bias_elems / 4 / 256);
        bias_out_kernel<<<nblocks, 256>>>(out + attn_elems);
    }
    // 6. flash attention (profiled launch)
    dim3 fgrid(SS/128, BB*HH);
    flash_mma_kernel<<<fgrid, 256, FL_SMEM>>>();
    // 7. output projection -> fp32 out
    gemm_mma_kernel<<<dim3(8, 32, 1), 256, GEMM_SMEM>>>(
        pchi, pclo, pWthi + 3*WSLOT, pWtlo + 3*WSLOT,
        nullptr, nullptr, nullptr, nullptr, nullptr, nullptr, out, 1);
}